// round 6
// baseline (speedup 1.0000x reference)
#include <cuda_runtime.h>
#include <cuda_bf16.h>
#include <math.h>
#include <stdint.h>

#define NSQ 12
#define NTOK 32768
#define TLEN 8192
#define SPEC_STRIDE 68
#define SPEC_SMEM (2*256*SPEC_STRIDE*4)

__device__ float  g_M[8*65536];
__device__ float  g_bufA[8*65536];
__device__ float  g_bufB[8*65536];
__device__ float  g_fsp[NSQ+1][8][16];
__device__ float  g_inv_s;
__device__ float2 g_lam[64];
__device__ float2 g_lamL[64];
__device__ float  g_pi[NTOK*8];
__device__ float  g_v[(size_t)NTOK*128];
__device__ float  g_zscr[(size_t)NTOK*128];
__device__ float2 g_carry[4*64*64];
__device__ float2 g_Cin[4*64*64];
// W split images: [mix 3][m 8][img 2][kc 4][n 128][kp 16] u32 (bf16x2)
__device__ uint32_t g_Wsw[3*8*2*4*2048];

__device__ __forceinline__ uint32_t bfsplit_hi(float a, float b) {
    __nv_bfloat16 h0 = __float2bfloat16(a), h1 = __float2bfloat16(b);
    return (uint32_t)__bfloat16_as_ushort(h0) | ((uint32_t)__bfloat16_as_ushort(h1) << 16);
}
__device__ __forceinline__ uint32_t bfsplit_lo(float a, float b) {
    __nv_bfloat16 h0 = __float2bfloat16(a), h1 = __float2bfloat16(b);
    float r0 = a - __bfloat162float(h0), r1 = b - __bfloat162float(h1);
    __nv_bfloat16 l0 = __float2bfloat16(r0), l1 = __float2bfloat16(r1);
    return (uint32_t)__bfloat16_as_ushort(l0) | ((uint32_t)__bfloat16_as_ushort(l1) << 16);
}
__device__ __forceinline__ void mma_bf16(float* c, const uint32_t* a, const uint32_t* b) {
    asm volatile(
        "mma.sync.aligned.m16n8k16.row.col.f32.bf16.bf16.f32 "
        "{%0,%1,%2,%3},{%4,%5,%6,%7},{%8,%9},{%0,%1,%2,%3};"
        : "+f"(c[0]), "+f"(c[1]), "+f"(c[2]), "+f"(c[3])
        : "r"(a[0]), "r"(a[1]), "r"(a[2]), "r"(a[3]), "r"(b[0]), "r"(b[1]));
}
#define FMA2(d,a,b) asm("fma.rn.f32x2 %0,%1,%2,%0;":"+l"(d):"l"(a),"l"(b))

// -------- 1) assemble K_raw per expert (256x256) --------
__global__ __launch_bounds__(256) void prep_kernel(
    const float* __restrict__ rho_raw, const float* __restrict__ theta,
    const float* __restrict__ K12, const float* __restrict__ K21,
    const float* __restrict__ K22)
{
    int m = blockIdx.x;
    float* Mo = g_M + m*65536;
    for (int idx = threadIdx.x; idx < 65536; idx += 256) {
        int r = idx>>8, c = idx&255;
        float val;
        if (r < 128) {
            if (c < 128) {
                int pr=r>>1, pc=c>>1;
                if (pr != pc) val = 0.0f;
                else {
                    float rho = (1.0f/(1.0f+expf(-rho_raw[pr])))*(1.0f-0.001f);
                    float ct=cosf(theta[pr]), st=sinf(theta[pr]);
                    float v2 = ((r&1)==0) ? (((c&1)==0)?ct:-st) : (((c&1)==0)?st:ct);
                    val = rho*v2;
                }
            } else val = K12[m*16384 + r*128 + (c-128)];
        } else {
            if (c < 128) val = K21[m*16384 + (r-128)*128 + c];
            else         val = K22[m*16384 + (r-128)*128 + (c-128)];
        }
        Mo[idx] = val;
    }
}

// -------- 1b) split W into bf16 hi/lo images --------
__global__ __launch_bounds__(256) void wsplit_kernel(
    const float* __restrict__ K12, const float* __restrict__ K22,
    const float* __restrict__ K21)
{
    int b = blockIdx.x;            // 0..23
    int mix = b>>3, m = b&7;
    const float* src = (mix==0) ? K12 : ((mix==1) ? K22 : K21);
    uint32_t* base = g_Wsw + ((size_t)mix*8 + m)*16384;
    for (int it = threadIdx.x; it < 8192; it += 256) {
        int n = it>>6, kpg = it&63;
        const float2 w = *(const float2*)(src + (size_t)m*16384 + n*128 + kpg*2);
        int kc = kpg>>4, kp = kpg&15;
        int off = kc*2048 + n*16 + kp;
        base[off]        = bfsplit_hi(w.x, w.y);
        base[8192 + off] = bfsplit_lo(w.x, w.y);
    }
}

// -------- 2) spectral chain step: out = in^T in / fs_prev --------
// Full-depth staging (one sync), FFMA2 compute.
__global__ __launch_bounds__(256) void spec_kernel(int step)
{
    const float* in  = (step==0) ? g_M : ((step&1) ? g_bufA : g_bufB);
    float*       out = (step&1) ? g_bufB : g_bufA;
    extern __shared__ float ssp[];
    float* As = ssp;                       // [256][68] cols i0..
    float* Bs = ssp + 256*SPEC_STRIDE;     // [256][68] cols j0..
    __shared__ float red[256];

    int m = blockIdx.y, bx = blockIdx.x;
    int i0 = (bx&3)*64, j0 = (bx>>2)*64;
    const float* Ain = in + m*65536;
    int tid = threadIdx.x, tx = tid&15, ty = tid>>4;
    {
        int kr = tid>>4, c4 = (tid&15)*4;
#pragma unroll
        for (int p = 0; p < 16; p++) {
            int k = p*16 + kr;
            *(float4*)&As[k*SPEC_STRIDE + c4] = *(const float4*)(Ain + k*256 + i0 + c4);
            *(float4*)&Bs[k*SPEC_STRIDE + c4] = *(const float4*)(Ain + k*256 + j0 + c4);
        }
    }
    __syncthreads();

    unsigned long long acc2[4][2];
#pragma unroll
    for (int r=0;r<4;r++) { acc2[r][0]=0ull; acc2[r][1]=0ull; }

#pragma unroll 4
    for (int k = 0; k < 256; k++) {
        float4 av = *(float4*)&As[k*SPEC_STRIDE + ty*4];
        unsigned long long b0 = *(unsigned long long*)&Bs[k*SPEC_STRIDE + tx*4];
        unsigned long long b1 = *(unsigned long long*)&Bs[k*SPEC_STRIDE + tx*4 + 2];
        float avv[4] = {av.x, av.y, av.z, av.w};
#pragma unroll
        for (int r = 0; r < 4; r++) {
            unsigned long long aa;
            asm("mov.b64 %0,{%1,%1};":"=l"(aa):"r"(__float_as_uint(avv[r])));
            FMA2(acc2[r][0], aa, b0);
            FMA2(acc2[r][1], aa, b1);
        }
    }

    float inv = 1.0f;
    if (step > 0) {
        float s = 0.0f;
#pragma unroll
        for (int t=0;t<16;t++) s += g_fsp[step-1][m][t];
        inv = 1.0f/s;
    }
    float lsum = 0.0f;
    float* Oo = out + m*65536;
#pragma unroll
    for (int r=0;r<4;r++) {
        float4 o;
        unsigned lo, hi;
        asm("mov.b64 {%0,%1},%2;":"=r"(lo),"=r"(hi):"l"(acc2[r][0]));
        o.x = __uint_as_float(lo)*inv; o.y = __uint_as_float(hi)*inv;
        asm("mov.b64 {%0,%1},%2;":"=r"(lo),"=r"(hi):"l"(acc2[r][1]));
        o.z = __uint_as_float(lo)*inv; o.w = __uint_as_float(hi)*inv;
        lsum += o.x*o.x+o.y*o.y+o.z*o.z+o.w*o.w;
        *(float4*)(Oo+(i0+ty*4+r)*256+j0+tx*4) = o;
    }
    red[tid]=lsum; __syncthreads();
    for (int s2=128;s2>0;s2>>=1) { if (tid<s2) red[tid]+=red[tid+s2]; __syncthreads(); }
    if (tid==0) g_fsp[step][m][bx]=red[0];
}

// -------- 3) finalize: sigma, scale, lambda --------
__global__ __launch_bounds__(64) void finalize_kernel(
    const float* __restrict__ rho_raw, const float* __restrict__ theta)
{
    __shared__ float s_sig[8];
    __shared__ float s_inv;
    int tid = threadIdx.x;
    if (tid < 8) {
        double lnl = 0.0, w = 1.0;
        for (int j=0;j<=NSQ;j++) {
            float fs = 0.0f;
            for (int t=0;t<16;t++) fs += g_fsp[j][tid][t];
            lnl += w*0.5*log((double)fs);
            w *= 0.5;
        }
        s_sig[tid] = (float)exp(0.5*lnl);
    }
    __syncthreads();
    if (tid == 0) {
        float s = 1.0f;
        for (int m=0;m<8;m++) s = fmaxf(s, s_sig[m]);
        s_inv = 1.0f/s;
        g_inv_s = s_inv;
    }
    __syncthreads();
    float rho = (1.0f/(1.0f+expf(-rho_raw[tid])))*(1.0f-0.001f);
    float mag = rho*s_inv;
    float th = theta[tid];
    float2 lam = make_float2(mag*cosf(th), mag*sinf(th));
    g_lam[tid] = lam;
    float2 q = lam;
    for (int i=0;i<7;i++) {
        float qr=q.x*q.x-q.y*q.y, qi=2.0f*q.x*q.y;
        q = make_float2(qr,qi);
    }
    g_lamL[tid] = q;
}

// -------- 4) gating softmax --------
__global__ __launch_bounds__(256) void gate_kernel(
    const float* __restrict__ u, const float* __restrict__ gw,
    const float* __restrict__ gb)
{
    __shared__ float sgw[1024];
    __shared__ float sgb[8];
    int tid = threadIdx.x;
    for (int i=tid;i<1024;i+=256) sgw[i]=gw[i];
    if (tid < 8) sgb[tid]=gb[tid];
    __syncthreads();
    int warp = tid>>5, lane = tid&31;
    int tok = blockIdx.x*8 + warp;
    float4 uv = ((const float4*)(u+(size_t)tok*128))[lane];
    float lg[8];
#pragma unroll
    for (int m=0;m<8;m++) {
        float4 w = ((const float4*)(sgw+m*128))[lane];
        float d = uv.x*w.x+uv.y*w.y+uv.z*w.z+uv.w*w.w;
#pragma unroll
        for (int s=16;s;s>>=1) d += __shfl_xor_sync(0xffffffffu,d,s);
        lg[m] = d + sgb[m];
    }
    float mx = lg[0];
#pragma unroll
    for (int m=1;m<8;m++) mx=fmaxf(mx,lg[m]);
    float e[8]; float sum=0.0f;
#pragma unroll
    for (int m=0;m<8;m++){ e[m]=expf(lg[m]-mx); sum+=e[m]; }
    float inv = 1.0f/sum;
#pragma unroll
    for (int m=0;m<8;m++)
        if (lane==m) g_pi[(size_t)tok*8+m] = e[m]*inv;
}

// -------- 5) mixture GEMM via mma.sync (bf16 hi/lo split, 3 terms) --------
__global__ void __launch_bounds__(256, 2) mix_mma_kernel(
    const float* __restrict__ A, const uint32_t* __restrict__ W,
    float* __restrict__ dst, int accumulate)
{
    __shared__ float    pis[128*8];
    __shared__ uint32_t Asm[2][128*20];
    __shared__ uint32_t Wsm[2][128*20];

    int tid = threadIdx.x, wid = tid>>5, lane = tid&31;
    int r4 = lane>>2, l4 = lane&3;
    int wm = wid>>2, wn = wid&3;
    int row0 = blockIdx.x*128;

    {
        const float4* gp = (const float4*)(g_pi + (size_t)row0*8);
        float4* sp = (float4*)pis;
        for (int i=tid;i<256;i+=256) sp[i] = gp[i];
    }

    float acc[4][4][4];
#pragma unroll
    for (int mt=0;mt<4;mt++)
#pragma unroll
        for (int nt=0;nt<4;nt++)
#pragma unroll
            for (int q=0;q<4;q++) acc[mt][nt][q]=0.0f;

    for (int m = 0; m < 8; m++) {
        for (int kc = 0; kc < 4; kc++) {
            __syncthreads();
#pragma unroll
            for (int it = 0; it < 8; it++) {
                int idx = tid + it*256;
                int row = idx>>4, kp = idx&15;
                float2 a = *(const float2*)(A + (size_t)(row0+row)*128 + kc*32 + kp*2);
                float pim = pis[row*8+m];
                float v0 = a.x*pim, v1 = a.y*pim;
                Asm[0][row*20+kp] = bfsplit_hi(v0, v1);
                Asm[1][row*20+kp] = bfsplit_lo(v0, v1);
            }
            {
                const uint32_t* wsrc = W + (size_t)m*16384 + kc*2048;
#pragma unroll
                for (int it = 0; it < 8; it++) {
                    int idx = tid + it*256;
                    int n = idx>>4, kp = idx&15;
                    Wsm[0][n*20+kp] = wsrc[idx];
                    Wsm[1][n*20+kp] = wsrc[8192 + idx];
                }
            }
            __syncthreads();

#pragma unroll
            for (int ks = 0; ks < 2; ks++) {
                uint32_t aH[4][4], aL[4][4], bH[4][2], bL[4][2];
#pragma unroll
                for (int mt = 0; mt < 4; mt++) {
                    int row = wm*64 + mt*16 + r4;
                    int kp = ks*8 + l4;
                    aH[mt][0] = Asm[0][row*20+kp];
                    aH[mt][1] = Asm[0][(row+8)*20+kp];
                    aH[mt][2] = Asm[0][row*20+kp+4];
                    aH[mt][3] = Asm[0][(row+8)*20+kp+4];
                    aL[mt][0] = Asm[1][row*20+kp];
                    aL[mt][1] = Asm[1][(row+8)*20+kp];
                    aL[mt][2] = Asm[1][row*20+kp+4];
                    aL[mt][3] = Asm[1][(row+8)*20+kp+4];
                }
#pragma unroll
                for (int nt = 0; nt < 4; nt++) {
                    int n = wn*32 + nt*8 + r4;
                    int kp = ks*8 + l4;
                    bH[nt][0] = Wsm[0][n*20+kp];
                    bH[nt][1] = Wsm[0][n*20+kp+4];
                    bL[nt][0] = Wsm[1][n*20+kp];
                    bL[nt][1] = Wsm[1][n*20+kp+4];
                }
#pragma unroll
                for (int mt = 0; mt < 4; mt++)
#pragma unroll
                    for (int nt = 0; nt < 4; nt++) {
                        mma_bf16(acc[mt][nt], aH[mt], bH[nt]);
                        mma_bf16(acc[mt][nt], aH[mt], bL[nt]);
                        mma_bf16(acc[mt][nt], aL[mt], bH[nt]);
                    }
            }
        }
    }

    float sc = g_inv_s;
#pragma unroll
    for (int mt = 0; mt < 4; mt++)
#pragma unroll
        for (int nt = 0; nt < 4; nt++) {
            int row = row0 + wm*64 + mt*16 + r4;
            int col = wn*32 + nt*8 + l4*2;
            float2* p0 = (float2*)(dst + (size_t)row*128 + col);
            float2* p1 = (float2*)(dst + (size_t)(row+8)*128 + col);
            float2 o0 = make_float2(acc[mt][nt][0]*sc, acc[mt][nt][1]*sc);
            float2 o1 = make_float2(acc[mt][nt][2]*sc, acc[mt][nt][3]*sc);
            if (accumulate) {
                float2 e0 = *p0, e1 = *p1;
                o0.x += e0.x; o0.y += e0.y;
                o1.x += e1.x; o1.y += e1.y;
            }
            *p0 = o0; *p1 = o1;
        }
}

// -------- 6) chunked complex scan --------
__global__ __launch_bounds__(64) void scanA_kernel()
{
    int b = blockIdx.x>>6, c = blockIdx.x&63, p = threadIdx.x;
    float2 lam = g_lam[p];
    const float2* vp = (const float2*)g_v + (size_t)(b*TLEN+c*128)*64 + p;
    float2 w = make_float2(0.0f,0.0f);
    for (int t=0;t<128;t++) {
        float2 x = vp[(size_t)t*64];
        float wr = fmaf(lam.x,w.x,fmaf(-lam.y,w.y,x.x));
        float wi = fmaf(lam.x,w.y,fmaf(lam.y,w.x,x.y));
        w = make_float2(wr,wi);
    }
    g_carry[(b*64+c)*64+p] = w;
}

__global__ __launch_bounds__(256) void scanB_kernel()
{
    int tid = threadIdx.x;
    int b = tid>>6, p = tid&63;
    float2 q = g_lamL[p];
    float2 w = make_float2(0.0f,0.0f);
    for (int c=0;c<64;c++) {
        g_Cin[(b*64+c)*64+p] = w;
        float2 s = g_carry[(b*64+c)*64+p];
        float wr = fmaf(q.x,w.x,fmaf(-q.y,w.y,s.x));
        float wi = fmaf(q.x,w.y,fmaf(q.y,w.x,s.y));
        w = make_float2(wr,wi);
    }
}

__global__ __launch_bounds__(64) void scanC_kernel(float* __restrict__ zout)
{
    int b = blockIdx.x>>6, c = blockIdx.x&63, p = threadIdx.x;
    float2 lam = g_lam[p];
    float2 w = g_Cin[(b*64+c)*64+p];
    const float2* vp = (const float2*)g_v + (size_t)(b*TLEN+c*128)*64 + p;
    float2* zp = (float2*)zout + (size_t)(b*TLEN+c*128)*64 + p;
    for (int t=0;t<128;t++) {
        float2 x = vp[(size_t)t*64];
        zp[(size_t)t*64] = w;
        float wr = fmaf(lam.x,w.x,fmaf(-lam.y,w.y,x.x));
        float wi = fmaf(lam.x,w.y,fmaf(lam.y,w.x,x.y));
        w = make_float2(wr,wi);
    }
}

extern "C" void kernel_launch(void* const* d_in, const int* in_sizes, int n_in,
                              void* d_out, int out_size)
{
    const float* u   = (const float*)d_in[0];
    const float* rho = (const float*)d_in[1];
    const float* th  = (const float*)d_in[2];
    const float* K12 = (const float*)d_in[3];
    const float* K21 = (const float*)d_in[4];
    const float* K22 = (const float*)d_in[5];
    const float* gw  = (const float*)d_in[6];
    const float* gb  = (const float*)d_in[7];
    float* out = (float*)d_out;

    float* zdst;
    if (out_size >= 2*4194304) {
        zdst = out + (size_t)4194304;
    } else {
        void* p; cudaGetSymbolAddress(&p, g_zscr);
        zdst = (float*)p;
    }
    void* pW; cudaGetSymbolAddress(&pW, g_Wsw);
    void* pV; cudaGetSymbolAddress(&pV, g_v);
    const uint32_t* Wbase = (const uint32_t*)pW;
    float* vptr = (float*)pV;

    cudaFuncSetAttribute(spec_kernel,
        cudaFuncAttributeMaxDynamicSharedMemorySize, SPEC_SMEM);

    prep_kernel<<<8,256>>>(rho, th, K12, K21, K22);
    wsplit_kernel<<<24,256>>>(K12, K22, K21);
    for (int s=0;s<=NSQ;s++) spec_kernel<<<dim3(16,8),256,SPEC_SMEM>>>(s);
    finalize_kernel<<<1,64>>>(rho, th);
    gate_kernel<<<4096,256>>>(u, gw, gb);

    mix_mma_kernel<<<256,256>>>(u, Wbase + 0,      vptr, 0);  // v = pi*K12*u
    scanA_kernel<<<256,64>>>();
    scanB_kernel<<<1,256>>>();
    scanC_kernel<<<256,64>>>(zdst);                           // z
    mix_mma_kernel<<<256,256>>>(u,    Wbase + 131072, out, 0); // y  = pi*K22*u
    mix_mma_kernel<<<256,256>>>(zdst, Wbase + 262144, out, 1); // y += pi*K21*z
}

// round 7
// speedup vs baseline: 1.6888x; 1.6888x over previous
#include <cuda_runtime.h>
#include <cuda_bf16.h>
#include <math.h>
#include <stdint.h>

#define NSQ 12
#define NTOK 32768
#define TLEN 8192

__device__ float  g_M[8*65536];
__device__ float  g_bufA[8*65536];
__device__ float  g_bufB[8*65536];
__device__ float  g_fsp[NSQ+1][8][16];
__device__ float  g_inv_s;
__device__ float2 g_lam[64];
__device__ float2 g_lamL[64];
__device__ float  g_pi[NTOK*8];
__device__ float  g_v[(size_t)NTOK*128];
__device__ float  g_zscr[(size_t)NTOK*128];
__device__ float2 g_carry[4*64*64];
__device__ float2 g_Cin[4*64*64];
// W split images: [mix 3][m 8][img 2][kc 4][n 128][kp 16] u32 (bf16x2)
__device__ uint32_t g_Wsw[3*8*2*4*2048];

__device__ __forceinline__ uint32_t bfsplit_hi(float a, float b) {
    __nv_bfloat16 h0 = __float2bfloat16(a), h1 = __float2bfloat16(b);
    return (uint32_t)__bfloat16_as_ushort(h0) | ((uint32_t)__bfloat16_as_ushort(h1) << 16);
}
__device__ __forceinline__ uint32_t bfsplit_lo(float a, float b) {
    __nv_bfloat16 h0 = __float2bfloat16(a), h1 = __float2bfloat16(b);
    float r0 = a - __bfloat162float(h0), r1 = b - __bfloat162float(h1);
    __nv_bfloat16 l0 = __float2bfloat16(r0), l1 = __float2bfloat16(r1);
    return (uint32_t)__bfloat16_as_ushort(l0) | ((uint32_t)__bfloat16_as_ushort(l1) << 16);
}
__device__ __forceinline__ void mma_bf16(float* c, const uint32_t* a, const uint32_t* b) {
    asm volatile(
        "mma.sync.aligned.m16n8k16.row.col.f32.bf16.bf16.f32 "
        "{%0,%1,%2,%3},{%4,%5,%6,%7},{%8,%9},{%0,%1,%2,%3};"
        : "+f"(c[0]), "+f"(c[1]), "+f"(c[2]), "+f"(c[3])
        : "r"(a[0]), "r"(a[1]), "r"(a[2]), "r"(a[3]), "r"(b[0]), "r"(b[1]));
}

// -------- 1) assemble K_raw per expert (256x256) --------
__global__ __launch_bounds__(256) void prep_kernel(
    const float* __restrict__ rho_raw, const float* __restrict__ theta,
    const float* __restrict__ K12, const float* __restrict__ K21,
    const float* __restrict__ K22)
{
    int m = blockIdx.x;
    float* Mo = g_M + m*65536;
    for (int idx = threadIdx.x; idx < 65536; idx += 256) {
        int r = idx>>8, c = idx&255;
        float val;
        if (r < 128) {
            if (c < 128) {
                int pr=r>>1, pc=c>>1;
                if (pr != pc) val = 0.0f;
                else {
                    float rho = (1.0f/(1.0f+expf(-rho_raw[pr])))*(1.0f-0.001f);
                    float ct=cosf(theta[pr]), st=sinf(theta[pr]);
                    float v2 = ((r&1)==0) ? (((c&1)==0)?ct:-st) : (((c&1)==0)?st:ct);
                    val = rho*v2;
                }
            } else val = K12[m*16384 + r*128 + (c-128)];
        } else {
            if (c < 128) val = K21[m*16384 + (r-128)*128 + c];
            else         val = K22[m*16384 + (r-128)*128 + (c-128)];
        }
        Mo[idx] = val;
    }
}

// -------- 1b) split W into bf16 hi/lo images --------
__global__ __launch_bounds__(256) void wsplit_kernel(
    const float* __restrict__ K12, const float* __restrict__ K22,
    const float* __restrict__ K21)
{
    int b = blockIdx.x;            // 0..23
    int mix = b>>3, m = b&7;
    const float* src = (mix==0) ? K12 : ((mix==1) ? K22 : K21);
    uint32_t* base = g_Wsw + ((size_t)mix*8 + m)*16384;
    for (int it = threadIdx.x; it < 8192; it += 256) {
        int n = it>>6, kpg = it&63;
        const float2 w = *(const float2*)(src + (size_t)m*16384 + n*128 + kpg*2);
        int kc = kpg>>4, kp = kpg&15;
        int off = kc*2048 + n*16 + kp;
        base[off]        = bfsplit_hi(w.x, w.y);
        base[8192 + off] = bfsplit_lo(w.x, w.y);
    }
}

// -------- 2) spectral chain step (R5 proven version) --------
__global__ __launch_bounds__(256) void spec_kernel(int step)
{
    const float* in  = (step==0) ? g_M : ((step&1) ? g_bufA : g_bufB);
    float*       out = (step&1) ? g_bufB : g_bufA;
    __shared__ float Ats[16][68];
    __shared__ float Bts[16][68];
    __shared__ float red[256];
    int m = blockIdx.y, bx = blockIdx.x;
    int i0 = (bx&3)*64, j0 = (bx>>2)*64;
    const float* Ain = in + m*65536;
    int tid = threadIdx.x, tx = tid&15, ty = tid>>4;
    int lk = tid>>4, l4 = (tid&15)*4;
    float acc[4][4];
#pragma unroll
    for (int r=0;r<4;r++)
#pragma unroll
        for (int c=0;c<4;c++) acc[r][c]=0.0f;
    for (int k0=0;k0<256;k0+=16) {
        __syncthreads();
        *(float4*)&Bts[lk][l4] = *(const float4*)(Ain+(k0+lk)*256+j0+l4);
        *(float4*)&Ats[lk][l4] = *(const float4*)(Ain+(k0+lk)*256+i0+l4);
        __syncthreads();
#pragma unroll
        for (int k=0;k<16;k++) {
            float4 a = *(float4*)&Ats[k][ty*4];
            float4 b = *(float4*)&Bts[k][tx*4];
            float av[4]={a.x,a.y,a.z,a.w}, bv[4]={b.x,b.y,b.z,b.w};
#pragma unroll
            for (int r=0;r<4;r++)
#pragma unroll
                for (int c=0;c<4;c++) acc[r][c]=fmaf(av[r],bv[c],acc[r][c]);
        }
    }
    float inv = 1.0f;
    if (step > 0) {
        float s = 0.0f;
#pragma unroll
        for (int t=0;t<16;t++) s += g_fsp[step-1][m][t];
        inv = 1.0f/s;
    }
    float lsum = 0.0f;
    float* Oo = out + m*65536;
#pragma unroll
    for (int r=0;r<4;r++) {
        float4 o;
        o.x=acc[r][0]*inv; o.y=acc[r][1]*inv; o.z=acc[r][2]*inv; o.w=acc[r][3]*inv;
        lsum += o.x*o.x+o.y*o.y+o.z*o.z+o.w*o.w;
        *(float4*)(Oo+(i0+ty*4+r)*256+j0+tx*4) = o;
    }
    red[tid]=lsum; __syncthreads();
    for (int s2=128;s2>0;s2>>=1) { if (tid<s2) red[tid]+=red[tid+s2]; __syncthreads(); }
    if (tid==0) g_fsp[step][m][bx]=red[0];
}

// -------- 3) finalize: sigma, scale, lambda --------
__global__ __launch_bounds__(64) void finalize_kernel(
    const float* __restrict__ rho_raw, const float* __restrict__ theta)
{
    __shared__ float s_sig[8];
    __shared__ float s_inv;
    int tid = threadIdx.x;
    if (tid < 8) {
        double lnl = 0.0, w = 1.0;
        for (int j=0;j<=NSQ;j++) {
            float fs = 0.0f;
            for (int t=0;t<16;t++) fs += g_fsp[j][tid][t];
            lnl += w*0.5*log((double)fs);
            w *= 0.5;
        }
        s_sig[tid] = (float)exp(0.5*lnl);
    }
    __syncthreads();
    if (tid == 0) {
        float s = 1.0f;
        for (int m=0;m<8;m++) s = fmaxf(s, s_sig[m]);
        s_inv = 1.0f/s;
        g_inv_s = s_inv;
    }
    __syncthreads();
    float rho = (1.0f/(1.0f+expf(-rho_raw[tid])))*(1.0f-0.001f);
    float mag = rho*s_inv;
    float th = theta[tid];
    float2 lam = make_float2(mag*cosf(th), mag*sinf(th));
    g_lam[tid] = lam;
    float2 q = lam;
    for (int i=0;i<7;i++) {
        float qr=q.x*q.x-q.y*q.y, qi=2.0f*q.x*q.y;
        q = make_float2(qr,qi);
    }
    g_lamL[tid] = q;
}

// -------- 4) gating softmax --------
__global__ __launch_bounds__(256) void gate_kernel(
    const float* __restrict__ u, const float* __restrict__ gw,
    const float* __restrict__ gb)
{
    __shared__ float sgw[1024];
    __shared__ float sgb[8];
    int tid = threadIdx.x;
    for (int i=tid;i<1024;i+=256) sgw[i]=gw[i];
    if (tid < 8) sgb[tid]=gb[tid];
    __syncthreads();
    int warp = tid>>5, lane = tid&31;
    int tok = blockIdx.x*8 + warp;
    float4 uv = ((const float4*)(u+(size_t)tok*128))[lane];
    float lg[8];
#pragma unroll
    for (int m=0;m<8;m++) {
        float4 w = ((const float4*)(sgw+m*128))[lane];
        float d = uv.x*w.x+uv.y*w.y+uv.z*w.z+uv.w*w.w;
#pragma unroll
        for (int s=16;s;s>>=1) d += __shfl_xor_sync(0xffffffffu,d,s);
        lg[m] = d + sgb[m];
    }
    float mx = lg[0];
#pragma unroll
    for (int m=1;m<8;m++) mx=fmaxf(mx,lg[m]);
    float e[8]; float sum=0.0f;
#pragma unroll
    for (int m=0;m<8;m++){ e[m]=expf(lg[m]-mx); sum+=e[m]; }
    float inv = 1.0f/sum;
#pragma unroll
    for (int m=0;m<8;m++)
        if (lane==m) g_pi[(size_t)tok*8+m] = e[m]*inv;
}

// -------- 5) mixture GEMM via mma.sync (bf16 hi/lo split, 3 terms) --------
// mode 0: dst = raw result (no scale)
// mode 2: dst = (dst + raw result) * g_inv_s
__global__ void __launch_bounds__(256, 2) mix_mma_kernel(
    const float* __restrict__ A, const uint32_t* __restrict__ W,
    float* __restrict__ dst, int mode)
{
    __shared__ float    pis[128*8];
    __shared__ uint32_t Asm[2][128*20];
    __shared__ uint32_t Wsm[2][128*20];

    int tid = threadIdx.x, wid = tid>>5, lane = tid&31;
    int r4 = lane>>2, l4 = lane&3;
    int wm = wid>>2, wn = wid&3;
    int row0 = blockIdx.x*128;

    {
        const float4* gp = (const float4*)(g_pi + (size_t)row0*8);
        float4* sp = (float4*)pis;
        for (int i=tid;i<256;i+=256) sp[i] = gp[i];
    }

    float acc[4][4][4];
#pragma unroll
    for (int mt=0;mt<4;mt++)
#pragma unroll
        for (int nt=0;nt<4;nt++)
#pragma unroll
            for (int q=0;q<4;q++) acc[mt][nt][q]=0.0f;

    for (int m = 0; m < 8; m++) {
        for (int kc = 0; kc < 4; kc++) {
            __syncthreads();
#pragma unroll
            for (int it = 0; it < 8; it++) {
                int idx = tid + it*256;
                int row = idx>>4, kp = idx&15;
                float2 a = *(const float2*)(A + (size_t)(row0+row)*128 + kc*32 + kp*2);
                float pim = pis[row*8+m];
                float v0 = a.x*pim, v1 = a.y*pim;
                Asm[0][row*20+kp] = bfsplit_hi(v0, v1);
                Asm[1][row*20+kp] = bfsplit_lo(v0, v1);
            }
            {
                const uint32_t* wsrc = W + (size_t)m*16384 + kc*2048;
#pragma unroll
                for (int it = 0; it < 8; it++) {
                    int idx = tid + it*256;
                    int n = idx>>4, kp = idx&15;
                    Wsm[0][n*20+kp] = wsrc[idx];
                    Wsm[1][n*20+kp] = wsrc[8192 + idx];
                }
            }
            __syncthreads();

#pragma unroll
            for (int ks = 0; ks < 2; ks++) {
                uint32_t aH[4][4], aL[4][4], bH[4][2], bL[4][2];
#pragma unroll
                for (int mt = 0; mt < 4; mt++) {
                    int row = wm*64 + mt*16 + r4;
                    int kp = ks*8 + l4;
                    aH[mt][0] = Asm[0][row*20+kp];
                    aH[mt][1] = Asm[0][(row+8)*20+kp];
                    aH[mt][2] = Asm[0][row*20+kp+4];
                    aH[mt][3] = Asm[0][(row+8)*20+kp+4];
                    aL[mt][0] = Asm[1][row*20+kp];
                    aL[mt][1] = Asm[1][(row+8)*20+kp];
                    aL[mt][2] = Asm[1][row*20+kp+4];
                    aL[mt][3] = Asm[1][(row+8)*20+kp+4];
                }
#pragma unroll
                for (int nt = 0; nt < 4; nt++) {
                    int n = wn*32 + nt*8 + r4;
                    int kp = ks*8 + l4;
                    bH[nt][0] = Wsm[0][n*20+kp];
                    bH[nt][1] = Wsm[0][n*20+kp+4];
                    bL[nt][0] = Wsm[1][n*20+kp];
                    bL[nt][1] = Wsm[1][n*20+kp+4];
                }
#pragma unroll
                for (int mt = 0; mt < 4; mt++)
#pragma unroll
                    for (int nt = 0; nt < 4; nt++) {
                        mma_bf16(acc[mt][nt], aH[mt], bH[nt]);
                        mma_bf16(acc[mt][nt], aH[mt], bL[nt]);
                        mma_bf16(acc[mt][nt], aL[mt], bH[nt]);
                    }
            }
        }
    }

    float sc = g_inv_s;
#pragma unroll
    for (int mt = 0; mt < 4; mt++)
#pragma unroll
        for (int nt = 0; nt < 4; nt++) {
            int row = row0 + wm*64 + mt*16 + r4;
            int col = wn*32 + nt*8 + l4*2;
            float2* p0 = (float2*)(dst + (size_t)row*128 + col);
            float2* p1 = (float2*)(dst + (size_t)(row+8)*128 + col);
            float2 o0, o1;
            if (mode == 2) {
                float2 e0 = *p0, e1 = *p1;
                o0 = make_float2((e0.x+acc[mt][nt][0])*sc, (e0.y+acc[mt][nt][1])*sc);
                o1 = make_float2((e1.x+acc[mt][nt][2])*sc, (e1.y+acc[mt][nt][3])*sc);
            } else {
                o0 = make_float2(acc[mt][nt][0], acc[mt][nt][1]);
                o1 = make_float2(acc[mt][nt][2], acc[mt][nt][3]);
            }
            *p0 = o0; *p1 = o1;
        }
}

// -------- 6) chunked complex scan (applies inv_s to v on the fly) --------
__global__ __launch_bounds__(64) void scanA_kernel()
{
    int b = blockIdx.x>>6, c = blockIdx.x&63, p = threadIdx.x;
    float2 lam = g_lam[p];
    float sc = g_inv_s;
    const float2* vp = (const float2*)g_v + (size_t)(b*TLEN+c*128)*64 + p;
    float2 w = make_float2(0.0f,0.0f);
    for (int t=0;t<128;t++) {
        float2 x = vp[(size_t)t*64];
        x.x *= sc; x.y *= sc;
        float wr = fmaf(lam.x,w.x,fmaf(-lam.y,w.y,x.x));
        float wi = fmaf(lam.x,w.y,fmaf(lam.y,w.x,x.y));
        w = make_float2(wr,wi);
    }
    g_carry[(b*64+c)*64+p] = w;
}

__global__ __launch_bounds__(256) void scanB_kernel()
{
    int tid = threadIdx.x;
    int b = tid>>6, p = tid&63;
    float2 q = g_lamL[p];
    float2 w = make_float2(0.0f,0.0f);
    for (int c=0;c<64;c++) {
        g_Cin[(b*64+c)*64+p] = w;
        float2 s = g_carry[(b*64+c)*64+p];
        float wr = fmaf(q.x,w.x,fmaf(-q.y,w.y,s.x));
        float wi = fmaf(q.x,w.y,fmaf(q.y,w.x,s.y));
        w = make_float2(wr,wi);
    }
}

__global__ __launch_bounds__(64) void scanC_kernel(float* __restrict__ zout)
{
    int b = blockIdx.x>>6, c = blockIdx.x&63, p = threadIdx.x;
    float2 lam = g_lam[p];
    float sc = g_inv_s;
    float2 w = g_Cin[(b*64+c)*64+p];
    const float2* vp = (const float2*)g_v + (size_t)(b*TLEN+c*128)*64 + p;
    float2* zp = (float2*)zout + (size_t)(b*TLEN+c*128)*64 + p;
    for (int t=0;t<128;t++) {
        float2 x = vp[(size_t)t*64];
        x.x *= sc; x.y *= sc;
        zp[(size_t)t*64] = w;
        float wr = fmaf(lam.x,w.x,fmaf(-lam.y,w.y,x.x));
        float wi = fmaf(lam.x,w.y,fmaf(lam.y,w.x,x.y));
        w = make_float2(wr,wi);
    }
}

extern "C" void kernel_launch(void* const* d_in, const int* in_sizes, int n_in,
                              void* d_out, int out_size)
{
    const float* u   = (const float*)d_in[0];
    const float* rho = (const float*)d_in[1];
    const float* th  = (const float*)d_in[2];
    const float* K12 = (const float*)d_in[3];
    const float* K21 = (const float*)d_in[4];
    const float* K22 = (const float*)d_in[5];
    const float* gw  = (const float*)d_in[6];
    const float* gb  = (const float*)d_in[7];
    float* out = (float*)d_out;

    float* zdst;
    if (out_size >= 2*4194304) {
        zdst = out + (size_t)4194304;
    } else {
        void* p; cudaGetSymbolAddress(&p, g_zscr);
        zdst = (float*)p;
    }
    void* pW; cudaGetSymbolAddress(&pW, g_Wsw);
    void* pV; cudaGetSymbolAddress(&pV, g_v);
    const uint32_t* Wbase = (const uint32_t*)pW;
    float* vptr = (float*)pV;

    // one-time side stream + events (created on first (correctness) call,
    // reused by the capture call; creation allocates no device memory)
    static cudaStream_t s1 = nullptr;
    static cudaEvent_t e0 = nullptr, e1 = nullptr;
    if (s1 == nullptr) {
        cudaStreamCreateWithFlags(&s1, cudaStreamNonBlocking);
        cudaEventCreateWithFlags(&e0, cudaEventDisableTiming);
        cudaEventCreateWithFlags(&e1, cudaEventDisableTiming);
    }

    // fork: side stream does the s-independent token-side work
    cudaEventRecord(e0, 0);
    cudaStreamWaitEvent(s1, e0, 0);
    wsplit_kernel<<<24,256,0,s1>>>(K12, K22, K21);
    gate_kernel<<<4096,256,0,s1>>>(u, gw, gb);
    mix_mma_kernel<<<256,256,0,s1>>>(u, Wbase + 0,      vptr, 0); // v_raw = pi*K12*u
    mix_mma_kernel<<<256,256,0,s1>>>(u, Wbase + 131072, out,  0); // y_raw = pi*K22*u
    cudaEventRecord(e1, s1);

    // main stream: spectral chain (the serialized critical path)
    prep_kernel<<<8,256>>>(rho, th, K12, K21, K22);
    for (int s=0;s<=NSQ;s++) spec_kernel<<<dim3(16,8),256>>>(s);
    finalize_kernel<<<1,64>>>(rho, th);

    // join, then scan (scaled) and final accumulate mix
    cudaStreamWaitEvent(0, e1, 0);
    scanA_kernel<<<256,64>>>();
    scanB_kernel<<<1,256>>>();
    scanC_kernel<<<256,64>>>(zdst);
    mix_mma_kernel<<<256,256>>>(zdst, Wbase + 262144, out, 2);    // out=(y_raw+pi*K21*z)*inv_s
}